// round 5
// baseline (speedup 1.0000x reference)
#include <cuda_runtime.h>

#define BATCH 16
#define CHN   64
#define HW    65536
#define HW4   (HW / 4)
#define NTHR  512
#define GRID  296        // 2 blocks/SM x 148 SMs: one wave, barrier safe
#define MAXSUB 19        // batches 0..7: 19 sub-blocks, 8..15: 18

// Per-(batch, sub-block) partials, written fresh each launch (no zeroing):
// [0]=max_s [1]=max_sq [2]=mean_s [3]=mean_sq [4]=min_s [5]=min_sq [6]=cnt
__device__ float g_part[BATCH][MAXSUB][8];
__device__ unsigned g_arrive = 0;
__device__ volatile unsigned g_release = 0;

__device__ __forceinline__ float warp_sum(float v) {
#pragma unroll
    for (int o = 16; o; o >>= 1) v += __shfl_xor_sync(0xffffffffu, v, o);
    return v;
}

__global__ void __launch_bounds__(NTHR, 2) fused_k(
    const float* __restrict__ x,
    const int*   __restrict__ mask,
    float*       __restrict__ out)
{
    // ---- block -> (batch, sub): batches 0..7 get 19 subs, 8..15 get 18 ----
    int b, sub, nsub;
    if (blockIdx.x < 152) { nsub = 19; b = blockIdx.x / 19;          sub = blockIdx.x % 19; }
    else                  { nsub = 18; b = 8 + (blockIdx.x-152)/18;  sub = (blockIdx.x-152)%18; }

    const int start = ( sub      * HW4) / nsub;
    const int end   = ((sub + 1) * HW4) / nsub;

    const int tid  = threadIdx.x;
    const int lane = tid & 31;
    const int wid  = tid >> 5;

    const float4* xb = reinterpret_cast<const float4*>(x)  + (size_t)b * CHN * HW4;
    const int4*   mb = reinterpret_cast<const int4*>(mask) + (size_t)b * HW4;
    float4*       ob = reinterpret_cast<float4*>(out)      + (size_t)b * 3 * HW4;

    float acc[7] = {0.f, 0.f, 0.f, 0.f, 0.f, 0.f, 0.f};

    // ---------------- Phase 1: pool + partial stats, xc -> out ----------------
#pragma unroll 1
    for (int p4 = start + tid; p4 < end; p4 += NTHR) {
        const float4* xp = xb + p4;

        float4 v = __ldcs(xp);      // streaming: x is read-once
        float4 vmax = v, vmin = v, vsum = v;
        // unroll 8: ~8 in-flight float4 loads/warp within a 64-reg budget
#pragma unroll 8
        for (int c = 1; c < CHN; ++c) {
            float4 t = __ldcs(xp + (size_t)c * HW4);
            vmax.x = fmaxf(vmax.x, t.x); vmax.y = fmaxf(vmax.y, t.y);
            vmax.z = fmaxf(vmax.z, t.z); vmax.w = fmaxf(vmax.w, t.w);
            vmin.x = fminf(vmin.x, t.x); vmin.y = fminf(vmin.y, t.y);
            vmin.z = fminf(vmin.z, t.z); vmin.w = fminf(vmin.w, t.w);
            vsum.x += t.x; vsum.y += t.y; vsum.z += t.z; vsum.w += t.w;
        }
        const float inv = 1.f / (float)CHN;
        float4 vmean = make_float4(vsum.x * inv, vsum.y * inv, vsum.z * inv, vsum.w * inv);

        ob[p4]           = vmax;
        ob[HW4 + p4]     = vmean;
        ob[2 * HW4 + p4] = vmin;

        int4 mk = mb[p4];
        float m0 = (mk.x == 1) ? 1.f : 0.f;
        float m1 = (mk.y == 1) ? 1.f : 0.f;
        float m2 = (mk.z == 1) ? 1.f : 0.f;
        float m3 = (mk.w == 1) ? 1.f : 0.f;

        acc[0] += vmax.x  * m0 + vmax.y  * m1 + vmax.z  * m2 + vmax.w  * m3;
        acc[1] += vmax.x * vmax.x * m0 + vmax.y * vmax.y * m1
                + vmax.z * vmax.z * m2 + vmax.w * vmax.w * m3;
        acc[2] += vmean.x * m0 + vmean.y * m1 + vmean.z * m2 + vmean.w * m3;
        acc[3] += vmean.x * vmean.x * m0 + vmean.y * vmean.y * m1
                + vmean.z * vmean.z * m2 + vmean.w * vmean.w * m3;
        acc[4] += vmin.x  * m0 + vmin.y  * m1 + vmin.z  * m2 + vmin.w  * m3;
        acc[5] += vmin.x * vmin.x * m0 + vmin.y * vmin.y * m1
                + vmin.z * vmin.z * m2 + vmin.w * vmin.w * m3;
        acc[6] += m0 + m1 + m2 + m3;
    }

    // Block-level reduction of acc -> g_part[b][sub]
    __shared__ float sh[16][7];
#pragma unroll
    for (int i = 0; i < 7; ++i) acc[i] = warp_sum(acc[i]);
    if (lane == 0) {
#pragma unroll
        for (int i = 0; i < 7; ++i) sh[wid][i] = acc[i];
    }
    __syncthreads();
    if (wid == 0) {
#pragma unroll
        for (int i = 0; i < 7; ++i) {
            float t = (lane < 16) ? sh[lane][i] : 0.f;
            t = warp_sum(t);
            if (lane == 0) g_part[b][sub][i] = t;
        }
    }

    // ---------------- Grid barrier (phase-flag, self-resetting) ----------------
    __syncthreads();
    if (tid == 0) {
        __threadfence();                       // publish g_part
        unsigned phase = g_release;            // stable until all GRID arrive
        unsigned old = atomicAdd(&g_arrive, 1);
        if (old == GRID - 1) {
            g_arrive = 0;
            __threadfence();
            g_release = phase + 1;
        } else {
            while (g_release == phase) { __nanosleep(128); }
        }
        __threadfence();
    }
    __syncthreads();

    // ---------------- Phase 2: final stats (<=19 partials, L2-hit) -------------
    __shared__ float s_stats[7];
    __shared__ float s_mean[3], s_rstd[3];
    if (tid < 7) {
        float v = 0.f;
        for (int r = 0; r < nsub; ++r) v += g_part[b][r][tid];
        s_stats[tid] = v;
    }
    __syncthreads();
    if (tid < 3) {
        const float cnt  = s_stats[6];
        const float s    = s_stats[2 * tid];
        const float sq   = s_stats[2 * tid + 1];
        const float mean = s / cnt;
        const float var  = (sq - s * mean) / (cnt - 1.f);
        s_mean[tid] = mean;
        s_rstd[tid] = rsqrtf(var);
    }
    __syncthreads();

    const float mean0 = s_mean[0], rstd0 = s_rstd[0];
    const float mean1 = s_mean[1], rstd1 = s_rstd[1];
    const float mean2 = s_mean[2], rstd2 = s_rstd[2];

    // ---------------- Phase 2: normalize in place (L2-resident xc/mask) --------
#pragma unroll 1
    for (int p4 = start + tid; p4 < end; p4 += NTHR) {
        int4 mk = mb[p4];

        float4 v0 = ob[p4];
        float4 v1 = ob[HW4 + p4];
        float4 v2 = ob[2 * HW4 + p4];

        v0.x = (mk.x == 1) ? (v0.x - mean0) * rstd0 : 0.f;
        v0.y = (mk.y == 1) ? (v0.y - mean0) * rstd0 : 0.f;
        v0.z = (mk.z == 1) ? (v0.z - mean0) * rstd0 : 0.f;
        v0.w = (mk.w == 1) ? (v0.w - mean0) * rstd0 : 0.f;

        v1.x = (mk.x == 1) ? (v1.x - mean1) * rstd1 : 0.f;
        v1.y = (mk.y == 1) ? (v1.y - mean1) * rstd1 : 0.f;
        v1.z = (mk.z == 1) ? (v1.z - mean1) * rstd1 : 0.f;
        v1.w = (mk.w == 1) ? (v1.w - mean1) * rstd1 : 0.f;

        v2.x = (mk.x == 1) ? (v2.x - mean2) * rstd2 : 0.f;
        v2.y = (mk.y == 1) ? (v2.y - mean2) * rstd2 : 0.f;
        v2.z = (mk.z == 1) ? (v2.z - mean2) * rstd2 : 0.f;
        v2.w = (mk.w == 1) ? (v2.w - mean2) * rstd2 : 0.f;

        ob[p4]           = v0;
        ob[HW4 + p4]     = v1;
        ob[2 * HW4 + p4] = v2;
    }
}

extern "C" void kernel_launch(void* const* d_in, const int* in_sizes, int n_in,
                              void* d_out, int out_size)
{
    const float* x;
    const int*   mask;
    if (in_sizes[0] > in_sizes[1]) {
        x    = (const float*)d_in[0];
        mask = (const int*)d_in[1];
    } else {
        x    = (const float*)d_in[1];
        mask = (const int*)d_in[0];
    }
    float* out = (float*)d_out;

    fused_k<<<GRID, NTHR>>>(x, mask, out);
}

// round 6
// speedup vs baseline: 1.0543x; 1.0543x over previous
#include <cuda_runtime.h>

#define BATCH 16
#define CHN   64
#define HW    65536
#define HW4   (HW / 4)
#define SUBS  16                   // blocks per batch
#define GRID  (BATCH * SUBS)       // 256 blocks, <=296 capacity -> one wave
#define NTHR  512
#define CPT   2                    // float4 columns per thread (1024 per block)

// Per-(batch, sub) partials, written fresh each launch (no zeroing):
// [0]=max_s [1]=max_sq [2]=mean_s [3]=mean_sq [4]=min_s [5]=min_sq [6]=cnt
__device__ float g_part[BATCH][SUBS][8];
__device__ unsigned g_arrive[BATCH] = {0};
__device__ volatile unsigned g_release[BATCH];

__device__ __forceinline__ float warp_sum(float v) {
#pragma unroll
    for (int o = 16; o; o >>= 1) v += __shfl_xor_sync(0xffffffffu, v, o);
    return v;
}

__global__ void __launch_bounds__(NTHR, 2) fused_k(
    const float* __restrict__ x,
    const int*   __restrict__ mask,
    float*       __restrict__ out)
{
    // Dynamic SMEM: pooled values parked on-SM. [CPT][3][NTHR] float4 = 48 KB.
    extern __shared__ float4 sp4[];

    const int b    = blockIdx.x >> 4;
    const int sub  = blockIdx.x & 15;
    const int tid  = threadIdx.x;
    const int lane = tid & 31;
    const int wid  = tid >> 5;

    const float4* xb = reinterpret_cast<const float4*>(x)  + (size_t)b * CHN * HW4;
    const int4*   mb = reinterpret_cast<const int4*>(mask) + (size_t)b * HW4;
    float4*       ob = reinterpret_cast<float4*>(out)      + (size_t)b * 3 * HW4;

    float acc[7] = {0.f, 0.f, 0.f, 0.f, 0.f, 0.f, 0.f};
    int4 mks[CPT];

    // ---------------- Phase 1: pool -> SMEM + partial stats (no gmem writes) ----
#pragma unroll 1
    for (int it = 0; it < CPT; ++it) {
        const int p4 = sub * (SUBS * 64) + it * NTHR + tid;   // sub*1024 + ...
        const float4* xp = xb + p4;

        float4 v = __ldcs(xp);      // streaming: x is read-once
        float4 vmax = v, vmin = v, vsum = v;
#pragma unroll 8
        for (int c = 1; c < CHN; ++c) {
            float4 t = __ldcs(xp + (size_t)c * HW4);
            vmax.x = fmaxf(vmax.x, t.x); vmax.y = fmaxf(vmax.y, t.y);
            vmax.z = fmaxf(vmax.z, t.z); vmax.w = fmaxf(vmax.w, t.w);
            vmin.x = fminf(vmin.x, t.x); vmin.y = fminf(vmin.y, t.y);
            vmin.z = fminf(vmin.z, t.z); vmin.w = fminf(vmin.w, t.w);
            vsum.x += t.x; vsum.y += t.y; vsum.z += t.z; vsum.w += t.w;
        }
        const float inv = 1.f / (float)CHN;
        float4 vmean = make_float4(vsum.x * inv, vsum.y * inv, vsum.z * inv, vsum.w * inv);

        // Park pooled values in SMEM (conflict-free: stride-1 in tid).
        sp4[(it * 3 + 0) * NTHR + tid] = vmax;
        sp4[(it * 3 + 1) * NTHR + tid] = vmean;
        sp4[(it * 3 + 2) * NTHR + tid] = vmin;

        int4 mk = mb[p4];
        mks[it] = mk;
        float m0 = (mk.x == 1) ? 1.f : 0.f;
        float m1 = (mk.y == 1) ? 1.f : 0.f;
        float m2 = (mk.z == 1) ? 1.f : 0.f;
        float m3 = (mk.w == 1) ? 1.f : 0.f;

        acc[0] += vmax.x  * m0 + vmax.y  * m1 + vmax.z  * m2 + vmax.w  * m3;
        acc[1] += vmax.x * vmax.x * m0 + vmax.y * vmax.y * m1
                + vmax.z * vmax.z * m2 + vmax.w * vmax.w * m3;
        acc[2] += vmean.x * m0 + vmean.y * m1 + vmean.z * m2 + vmean.w * m3;
        acc[3] += vmean.x * vmean.x * m0 + vmean.y * vmean.y * m1
                + vmean.z * vmean.z * m2 + vmean.w * vmean.w * m3;
        acc[4] += vmin.x  * m0 + vmin.y  * m1 + vmin.z  * m2 + vmin.w  * m3;
        acc[5] += vmin.x * vmin.x * m0 + vmin.y * vmin.y * m1
                + vmin.z * vmin.z * m2 + vmin.w * vmin.w * m3;
        acc[6] += m0 + m1 + m2 + m3;
    }

    // Block-level reduction of acc -> g_part[b][sub]
    __shared__ float sh[16][7];
#pragma unroll
    for (int i = 0; i < 7; ++i) acc[i] = warp_sum(acc[i]);
    if (lane == 0) {
#pragma unroll
        for (int i = 0; i < 7; ++i) sh[wid][i] = acc[i];
    }
    __syncthreads();
    if (wid == 0) {
#pragma unroll
        for (int i = 0; i < 7; ++i) {
            float t = (lane < 16) ? sh[lane][i] : 0.f;
            t = warp_sum(t);
            if (lane == 0) g_part[b][sub][i] = t;
        }
    }

    // ---------- Per-batch barrier (phase-flag, self-resetting, 16 arrivals) ----
    __syncthreads();
    if (tid == 0) {
        __threadfence();                          // publish g_part[b][sub]
        unsigned phase = g_release[b];            // stable until all SUBS arrive
        unsigned old = atomicAdd(&g_arrive[b], 1);
        if (old == SUBS - 1) {
            g_arrive[b] = 0;
            __threadfence();
            g_release[b] = phase + 1;
        } else {
            while (g_release[b] == phase) { __nanosleep(64); }
        }
        __threadfence();
    }
    __syncthreads();

    // ---------------- Final stats (16 partials, L2-hit) ------------------------
    __shared__ float s_stats[7];
    __shared__ float s_mean[3], s_rstd[3];
    if (tid < 7) {
        float v = 0.f;
#pragma unroll
        for (int r = 0; r < SUBS; ++r) v += g_part[b][r][tid];
        s_stats[tid] = v;
    }
    __syncthreads();
    if (tid < 3) {
        const float cnt  = s_stats[6];
        const float s    = s_stats[2 * tid];
        const float sq   = s_stats[2 * tid + 1];
        const float mean = s / cnt;
        const float var  = (sq - s * mean) / (cnt - 1.f);
        s_mean[tid] = mean;
        s_rstd[tid] = rsqrtf(var);
    }
    __syncthreads();

    const float mean0 = s_mean[0], rstd0 = s_rstd[0];
    const float mean1 = s_mean[1], rstd1 = s_rstd[1];
    const float mean2 = s_mean[2], rstd2 = s_rstd[2];

    // ---------------- Phase 2: normalize from SMEM, write final out ------------
#pragma unroll
    for (int it = 0; it < CPT; ++it) {
        const int p4 = sub * (SUBS * 64) + it * NTHR + tid;
        const int4 mk = mks[it];

        float4 v0 = sp4[(it * 3 + 0) * NTHR + tid];
        float4 v1 = sp4[(it * 3 + 1) * NTHR + tid];
        float4 v2 = sp4[(it * 3 + 2) * NTHR + tid];

        v0.x = (mk.x == 1) ? (v0.x - mean0) * rstd0 : 0.f;
        v0.y = (mk.y == 1) ? (v0.y - mean0) * rstd0 : 0.f;
        v0.z = (mk.z == 1) ? (v0.z - mean0) * rstd0 : 0.f;
        v0.w = (mk.w == 1) ? (v0.w - mean0) * rstd0 : 0.f;

        v1.x = (mk.x == 1) ? (v1.x - mean1) * rstd1 : 0.f;
        v1.y = (mk.y == 1) ? (v1.y - mean1) * rstd1 : 0.f;
        v1.z = (mk.z == 1) ? (v1.z - mean1) * rstd1 : 0.f;
        v1.w = (mk.w == 1) ? (v1.w - mean1) * rstd1 : 0.f;

        v2.x = (mk.x == 1) ? (v2.x - mean2) * rstd2 : 0.f;
        v2.y = (mk.y == 1) ? (v2.y - mean2) * rstd2 : 0.f;
        v2.z = (mk.z == 1) ? (v2.z - mean2) * rstd2 : 0.f;
        v2.w = (mk.w == 1) ? (v2.w - mean2) * rstd2 : 0.f;

        ob[p4]           = v0;
        ob[HW4 + p4]     = v1;
        ob[2 * HW4 + p4] = v2;
    }
}

extern "C" void kernel_launch(void* const* d_in, const int* in_sizes, int n_in,
                              void* d_out, int out_size)
{
    const float* x;
    const int*   mask;
    if (in_sizes[0] > in_sizes[1]) {
        x    = (const float*)d_in[0];
        mask = (const int*)d_in[1];
    } else {
        x    = (const float*)d_in[1];
        mask = (const int*)d_in[0];
    }
    float* out = (float*)d_out;

    const int smem = CPT * 3 * NTHR * sizeof(float4);   // 48 KB dynamic
    static bool configured = false;
    if (!configured) {
        cudaFuncSetAttribute(fused_k, cudaFuncAttributeMaxDynamicSharedMemorySize, smem);
        configured = true;
    }
    fused_k<<<GRID, NTHR, smem>>>(x, mask, out);
}